// round 16
// baseline (speedup 1.0000x reference)
#include <cuda_runtime.h>

#define NN 8
#define CC 80
#define HH 160
#define WW 160
#define LL (HH*WW)           /* 25600 locations */
#define LQ (LL/4)            /* 6400 4-location chunks */
#define NQUART 4
#define CPQ (CC/NQUART)      /* 20 classes per scan slice */
#define KTOP 1000
#define KPAD 1024
#define CAP 2048
#define NSEG 64
#define SEGCAP 4096
#define POSTN 100
#define NBINS 2048           /* shift-12 bins; used 1..1229 */
#define NB_PAD 2052
#define BIN_BASE 0x3F333333u /* float bits of 0.7f */
#define BIN_SHIFT 12
#define IMG_MAX 1279.0f
#define XCLIP 4.135166556742356f
#define NMS_T 0.6f
#define FINF 3.0e38f

typedef unsigned long long u64;

// ---------------- scratch (static device globals; no allocation) -----------
__device__ unsigned g_hist[NN][NB_PAD];
__device__ unsigned g_cnt2[NN][NSEG];
__device__ u64      g_cand2[NN][NSEG][SEGCAP];
__device__ float4   g_xmn[NN * LQ];
__device__ float4   g_boxes[NN][KPAD];
__device__ float    g_sc[NN][KPAD];
__device__ int      g_cls[NN][KPAD];
__device__ unsigned g_smatch[NN][CC][32];            /* class -> rows bitmap */
__device__ unsigned g_mask[NN][KPAD][32];
__device__ unsigned g_done[NN];

__device__ __forceinline__ float sigf(float x) { return 1.0f / (1.0f + expf(-x)); }

// ---------------- kernel 1: prep — zero scratch/out + per-location xmin ----
__global__ void k_prep(const float* __restrict__ ctr, float* out, int out_size) {
    int t = blockIdx.x * blockDim.x + threadIdx.x;
    const int stride = gridDim.x * blockDim.x;
    for (int i = t; i < NN * NB_PAD; i += stride) ((unsigned*)g_hist)[i] = 0u;
    for (int i = t; i < NN * NSEG; i += stride) ((unsigned*)g_cnt2)[i] = 0u;
    for (int i = t; i < NN * CC * 32; i += stride) ((unsigned*)g_smatch)[i] = 0u;
    for (int i = t; i < NN; i += stride) g_done[i] = 0u;
    for (int i = t; i < out_size; i += stride) out[i] = 0.0f;
    if (t < NN * LQ) {
        float4 cv = ((const float4*)ctr)[t];
        float qv[4] = {cv.x, cv.y, cv.z, cv.w};
        float xr[4];
#pragma unroll
        for (int i = 0; i < 4; i++) {
            float q = sigf(qv[i]);
            if (q > 0.7f) {                       // p<1 so p*q>=0.7 needs q>0.7
                float r = 0.6999f / q;            // margined prefilter threshold
                xr[i] = logf(r / (1.0f - r));
            } else {
                xr[i] = FINF;
            }
        }
        g_xmn[t] = make_float4(xr[0], xr[1], xr[2], xr[3]);
    }
}

// ---------------- kernel 2: lean scan of box_cls (R12-frozen) --------------
__global__ void __launch_bounds__(256) k_scan(const float* __restrict__ cls,
                                              const float* __restrict__ ctr) {
    int n = blockIdx.z;
    int c4 = blockIdx.x * 256 + threadIdx.x;         // chunk within image
    int c0 = blockIdx.y * CPQ;                       // first class of quarter
    float4 xm = g_xmn[n * LQ + c4];
    if (xm.x > 1.0e30f && xm.y > 1.0e30f && xm.z > 1.0e30f && xm.w > 1.0e30f)
        return;                                      // chunk fully inactive
    const float4* p = (const float4*)cls + ((size_t)n * CC + c0) * LQ + c4;
#pragma unroll 4
    for (int c = 0; c < CPQ; c++) {
        float4 xv = p[(size_t)c * LQ];
        if (xv.x > xm.x || xv.y > xm.y || xv.z > xm.z || xv.w > xm.w) {
            float xa[4] = {xv.x, xv.y, xv.z, xv.w};
            float xmn[4] = {xm.x, xm.y, xm.z, xm.w};
#pragma unroll
            for (int i = 0; i < 4; i++) {
                if (xa[i] > xmn[i]) {
                    int loc = c4 * 4 + i;
                    float q = sigf(ctr[n * LL + loc]);
                    float s = q / (1.0f + expf(-xa[i]));
                    unsigned bits = __float_as_uint(s);
                    if (bits >= BIN_BASE) {
                        unsigned seg = ((unsigned)c4) & (NSEG - 1);
                        unsigned pos = atomicAdd(&g_cnt2[n][seg], 1u);
                        if (pos < SEGCAP) {
                            unsigned idx = (unsigned)(loc * CC + (c0 + c));
                            g_cand2[n][seg][pos] = ((u64)bits << 32) | (u64)(~idx);
                        }
                        unsigned bin = ((bits - BIN_BASE) >> BIN_SHIFT) + 1u;
                        atomicAdd(&g_hist[n][bin], 1u);
                    }
                }
            }
        }
    }
}

// ---------------- kernel 3: fused threshold + gather + sort + decode -------
__global__ void k_select(const float* __restrict__ anchors,
                         const float* __restrict__ reg) {
    __shared__ u64 sh[CAP];                          // 16 KB
    __shared__ unsigned swsum[32];
    __shared__ unsigned s_thr, s_cnt;
    int n = blockIdx.x, tid = threadIdx.x;           // 1024 threads
    int warp = tid >> 5, lane = tid & 31;
    for (int t = tid; t < CAP; t += 1024) sh[t] = 0ULL;
    if (tid == 0) { s_thr = 1u; s_cnt = 0u; }
    // --- threshold bin: two-level shfl scan over 2-bin chunks (top->down) ---
    int hi = NBINS - 2 * tid;                        // top bin of this chunk
    unsigned csum = g_hist[n][hi] + g_hist[n][hi - 1];
    unsigned incl = csum;
#pragma unroll
    for (int off = 1; off < 32; off <<= 1) {
        unsigned v = __shfl_up_sync(0xffffffffu, incl, off);
        if (lane >= off) incl += v;
    }
    if (lane == 31) swsum[warp] = incl;
    __syncthreads();
    if (warp == 0) {
        unsigned w = swsum[lane];
        unsigned wi = w;
#pragma unroll
        for (int off = 1; off < 32; off <<= 1) {
            unsigned v = __shfl_up_sync(0xffffffffu, wi, off);
            if (lane >= off) wi += v;
        }
        swsum[lane] = wi - w;                        // exclusive warp base
    }
    __syncthreads();
    unsigned run = swsum[warp] + incl - csum;        // count strictly above chunk
#pragma unroll
    for (int o = 0; o < 2; o++) {
        unsigned h = g_hist[n][hi - o];
        run += h;
        if (run >= (unsigned)KTOP && run - h < (unsigned)KTOP)
            s_thr = (unsigned)(hi - o);              // unique crossing
    }
    __syncthreads();
    unsigned edge = BIN_BASE + ((s_thr - 1u) << BIN_SHIFT);
    // --- gather from segment lists (warp per segment, 2 segs per warp) ---
    for (int s = 0; s < 2; s++) {
        int seg = warp + 32 * s;
        unsigned cnt = g_cnt2[n][seg];
        if (cnt > SEGCAP) cnt = SEGCAP;
        for (unsigned j = lane; j < cnt; j += 32) {
            u64 key = g_cand2[n][seg][j];
            if ((unsigned)(key >> 32) >= edge) {
                unsigned pos = atomicAdd(&s_cnt, 1u);
                if (pos < CAP) sh[pos] = key;
            }
        }
    }
    __syncthreads();
    unsigned cnt = s_cnt;
    if (cnt > CAP) cnt = CAP;
    // --- hybrid bitonic sort desc, dynamic size 1024/2048 (cnt<=1024 common) ---
    int capx = (cnt <= 1024u) ? 1024 : 2048;         // block-uniform
    bool act = (tid < (capx >> 1));                  // warp-uniform
    u64 e0 = 0, e1 = 0;
    if (act) {
        e0 = sh[2 * tid]; e1 = sh[2 * tid + 1];
        for (int k = 2; k <= 32; k <<= 1) {          // all-register stages
            bool desc = (((2 * tid) & k) == 0);
            for (int j = k >> 1; j >= 2; j >>= 1) {
                bool keepmax = ((((2 * tid) & j) == 0) == desc);
                u64 p0 = __shfl_xor_sync(0xffffffffu, e0, j >> 1);
                u64 p1 = __shfl_xor_sync(0xffffffffu, e1, j >> 1);
                e0 = keepmax ? (e0 > p0 ? e0 : p0) : (e0 < p0 ? e0 : p0);
                e1 = keepmax ? (e1 > p1 ? e1 : p1) : (e1 < p1 ? e1 : p1);
            }
            if ((e0 < e1) == desc) { u64 tmp = e0; e0 = e1; e1 = tmp; }
        }
    }
    for (int k = 64; k <= capx; k <<= 1) {
        if (act) { sh[2 * tid] = e0; sh[2 * tid + 1] = e1; }
        __syncthreads();
        for (int j = k >> 1; j >= 32; j >>= 1) {     // smem stages
            if (act) {
                int i = ((tid & ~(j - 1)) << 1) | (tid & (j - 1));
                int p = i | j;
                u64 a = sh[i], b = sh[p];
                bool desc = ((i & k) == 0);
                if ((a < b) == desc) { sh[i] = b; sh[p] = a; }
            }
            __syncthreads();
        }
        if (act) {
            e0 = sh[2 * tid]; e1 = sh[2 * tid + 1];
            bool desc = (((2 * tid) & k) == 0);
            for (int j = 16; j >= 2; j >>= 1) {      // register tail
                bool keepmax = ((((2 * tid) & j) == 0) == desc);
                u64 p0 = __shfl_xor_sync(0xffffffffu, e0, j >> 1);
                u64 p1 = __shfl_xor_sync(0xffffffffu, e1, j >> 1);
                e0 = keepmax ? (e0 > p0 ? e0 : p0) : (e0 < p0 ? e0 : p0);
                e1 = keepmax ? (e1 > p1 ? e1 : p1) : (e1 < p1 ? e1 : p1);
            }
            if ((e0 < e1) == desc) { u64 tmp = e0; e0 = e1; e1 = tmp; }
        }
    }
    if (act) { sh[2 * tid] = e0; sh[2 * tid + 1] = e1; }
    __syncthreads();
    // --- decode top-1000 + build class->rows bitmap ---
    if (tid < KTOP) {
        if (tid < (int)cnt) {
            u64 key = sh[tid];
            unsigned bits = (unsigned)(key >> 32);
            unsigned idx = ~((unsigned)(key & 0xFFFFFFFFull));
            int loc = (int)(idx / CC);
            int c = (int)(idx % CC);
            float val = __uint_as_float(bits);
            float4 a = ((const float4*)anchors)[loc];
            float w  = a.z - a.x + 1.0f;
            float h  = a.w - a.y + 1.0f;
            float cx = a.x + 0.5f * w;
            float cy = a.y + 0.5f * h;
            float dx = reg[(size_t)(n * 4 + 0) * LL + loc] * 0.1f;
            float dy = reg[(size_t)(n * 4 + 1) * LL + loc] * 0.1f;
            float dw = fminf(reg[(size_t)(n * 4 + 2) * LL + loc] * 0.2f, XCLIP);
            float dh = fminf(reg[(size_t)(n * 4 + 3) * LL + loc] * 0.2f, XCLIP);
            float pcx = dx * w + cx;
            float pcy = dy * h + cy;
            float pw = expf(dw) * w;
            float ph = expf(dh) * h;
            float x1 = fminf(fmaxf(pcx - 0.5f * (pw - 1.0f), 0.0f), IMG_MAX);
            float y1 = fminf(fmaxf(pcy - 0.5f * (ph - 1.0f), 0.0f), IMG_MAX);
            float x2 = fminf(fmaxf(pcx + 0.5f * (pw - 1.0f), 0.0f), IMG_MAX);
            float y2 = fminf(fmaxf(pcy + 0.5f * (ph - 1.0f), 0.0f), IMG_MAX);
            g_boxes[n][tid] = make_float4(x1, y1, x2, y2);
            g_cls[n][tid] = c + 1;
            g_sc[n][tid] = sqrtf(val);
            atomicOr(&g_smatch[n][c][tid >> 5], 1u << (tid & 31));
        } else {
            g_boxes[n][tid] = make_float4(0.0f, 0.0f, 0.0f, 0.0f);
            g_cls[n][tid] = 0;
            g_sc[n][tid] = -1.0f;
        }
    }
}

// ---------------- kernel 4: mask + (last block) greedy NMS + output --------
// grid (32, NN) x 512 threads: 16 warps x 2 rows each = 32 rows/block;
// thread = (row, word). 512 threads -> 128-reg cap: NMS pf/nx stay in regs.
__global__ void __launch_bounds__(512) k_masknms(float* __restrict__ dets,
                                                 float* __restrict__ labels) {
    int n = blockIdx.y;
    int word = threadIdx.x & 31;
#pragma unroll
    for (int r = 0; r < 2; r++) {
        int i = blockIdx.x * 32 + (threadIdx.x >> 5) + 16 * r;   // row
        int ci = g_cls[n][i];
        int w0 = i >> 5;
        unsigned m = 0u;
        if (ci > 0 && word >= w0) {
            unsigned mw = g_smatch[n][ci - 1][word];
            if (word == w0) mw &= ~((2u << (i & 31)) - 1u);  // clear bits <= i
            if (mw) {
                float4 bi = g_boxes[n][i];
                float ai = fmaxf(bi.z - bi.x, 0.0f) * fmaxf(bi.w - bi.y, 0.0f);
                do {
                    int b = __ffs(mw) - 1;
                    mw &= mw - 1u;
                    int j = word * 32 + b;
                    float4 bj = g_boxes[n][j];
                    float aj = fmaxf(bj.z - bj.x, 0.0f) * fmaxf(bj.w - bj.y, 0.0f);
                    float lx = fmaxf(bi.x, bj.x), ly = fmaxf(bi.y, bj.y);
                    float rx = fminf(bi.z, bj.z), ry = fminf(bi.w, bj.w);
                    float iw = fmaxf(rx - lx, 0.0f), ih = fmaxf(ry - ly, 0.0f);
                    float inter = iw * ih;
                    float iou = inter / (ai + aj - inter + 1e-9f);
                    if (iou > NMS_T) m |= (1u << b);
                } while (mw);
            }
        }
        g_mask[n][i][word] = m;
    }
    // --- last-block election (threadfence-reduction pattern) ---
    __threadfence();
    __shared__ unsigned s_old;
    if (threadIdx.x == 0) s_old = atomicAdd(&g_done[n], 1u);
    __syncthreads();
    if (s_old != 31u) return;                        // not the last block
    __threadfence();                                 // acquire all g_mask stores
    if (threadIdx.x >= 32) return;
    // --- greedy NMS: 32 word-rounds, double-buffered register rows ---
    int lane = threadIdx.x;
    unsigned my_valid = 0u;
#pragma unroll
    for (int b = 0; b < 32; b++)
        if (g_sc[n][lane * 32 + b] > 0.0f) my_valid |= (1u << b);
    unsigned sup = 0u;
    unsigned pf[32], nx[32];
#pragma unroll
    for (int b = 0; b < 32; b++) pf[b] = g_mask[n][b][lane];
    for (int w = 0; w < 32; w++) {
        if (w < 31) {
#pragma unroll
            for (int b = 0; b < 32; b++) nx[b] = g_mask[n][(w + 1) * 32 + b][lane];
        }
        unsigned keep = 0u;
        if (lane == w) {                             // owner: serial intra-word
            unsigned s = sup;
#pragma unroll
            for (int b = 0; b < 32; b++) {
                unsigned bit = 1u << b;
                if ((my_valid & bit) && !(s & bit)) { keep |= bit; s |= pf[b]; }
            }
        }
        keep = __shfl_sync(0xffffffffu, keep, w);
#pragma unroll
        for (int b = 0; b < 32; b++)
            if (keep & (1u << b)) sup |= pf[b];
#pragma unroll
        for (int b = 0; b < 32; b++) pf[b] = nx[b];
    }
    // --- lane-parallel ranked output ---
    unsigned my_keep = my_valid & ~sup;
    int pc = __popc(my_keep);
    int pref = pc;
#pragma unroll
    for (int off = 1; off < 32; off <<= 1) {
        int v = __shfl_up_sync(0xffffffffu, pref, off);
        if (lane >= off) pref += v;
    }
    pref -= pc;                                      // exclusive prefix
    unsigned rem = my_keep;
    int local = 0;
    while (rem) {
        int b = __ffs(rem) - 1;
        rem &= rem - 1u;
        int rank = pref + local;
        local++;
        if (rank < POSTN) {
            int idx = lane * 32 + b;
            float4 bx = g_boxes[n][idx];
            float* d = dets + (size_t)(n * POSTN + rank) * 5;
            d[0] = bx.x; d[1] = bx.y; d[2] = bx.z; d[3] = bx.w;
            d[4] = g_sc[n][idx];
            if (labels) labels[n * POSTN + rank] = (float)g_cls[n][idx];
        }
    }
}

// ---------------- launch -----------------------------------------------------
extern "C" void kernel_launch(void* const* d_in, const int* in_sizes, int n_in,
                              void* d_out, int out_size) {
    const float* reg  = (const float*)d_in[0];  // [8,4,160,160]
    const float* ctr  = (const float*)d_in[1];  // [8,1,160,160]
    const float* cls  = (const float*)d_in[2];  // [8,80,160,160]
    const float* anch = (const float*)d_in[3];  // [25600,4]
    float* out = (float*)d_out;
    float* dets = out;
    float* labels = (out_size >= NN * POSTN * 6) ? out + (size_t)NN * POSTN * 5 : nullptr;

    k_prep<<<400, 256>>>(ctr, out, out_size);
    k_scan<<<dim3(LQ / 256, NQUART, NN), 256>>>(cls, ctr);
    k_select<<<NN, 1024>>>(anch, reg);
    k_masknms<<<dim3(32, NN), 512>>>(dets, labels);
}

// round 17
// speedup vs baseline: 1.0998x; 1.0998x over previous
#include <cuda_runtime.h>

#define NN 8
#define CC 80
#define HH 160
#define WW 160
#define LL (HH*WW)           /* 25600 locations */
#define LQ (LL/4)            /* 6400 4-location chunks */
#define NQUART 4
#define CPQ (CC/NQUART)      /* 20 classes per scan slice */
#define KTOP 1000
#define KPAD 1024
#define CAP 2048
#define NSEG 64
#define SEGCAP 4096
#define POSTN 100
#define NBINS 2048           /* shift-12 bins; used 1..1229 */
#define NB_PAD 2052
#define BIN_BASE 0x3F333333u /* float bits of 0.7f */
#define BIN_SHIFT 12
#define IMG_MAX 1279.0f
#define XCLIP 4.135166556742356f
#define NMS_T 0.6f
#define FINF 3.0e38f
#define NMS_SMEM (KPAD * 32 * 4)   /* 131072 B */

typedef unsigned long long u64;

// ---------------- scratch (static device globals; no allocation) -----------
__device__ unsigned g_hist[NN][NB_PAD];
__device__ unsigned g_cnt2[NN][NSEG];
__device__ u64      g_cand2[NN][NSEG][SEGCAP];
__device__ float4   g_xmn[NN * LQ];
__device__ float4   g_boxes[NN][KPAD];
__device__ float    g_sc[NN][KPAD];
__device__ int      g_cls[NN][KPAD];
__device__ unsigned g_smatch[NN][CC][32];            /* class -> rows bitmap */
__device__ unsigned g_mask[NN][KPAD][32];

__device__ __forceinline__ float sigf(float x) { return 1.0f / (1.0f + expf(-x)); }

// ---------------- kernel 1: prep — zero scratch/out + per-location xmin ----
__global__ void k_prep(const float* __restrict__ ctr, float* out, int out_size) {
    int t = blockIdx.x * blockDim.x + threadIdx.x;
    const int stride = gridDim.x * blockDim.x;
    for (int i = t; i < NN * NB_PAD; i += stride) ((unsigned*)g_hist)[i] = 0u;
    for (int i = t; i < NN * NSEG; i += stride) ((unsigned*)g_cnt2)[i] = 0u;
    for (int i = t; i < NN * CC * 32; i += stride) ((unsigned*)g_smatch)[i] = 0u;
    for (int i = t; i < out_size; i += stride) out[i] = 0.0f;
    if (t < NN * LQ) {
        float4 cv = ((const float4*)ctr)[t];
        float qv[4] = {cv.x, cv.y, cv.z, cv.w};
        float xr[4];
#pragma unroll
        for (int i = 0; i < 4; i++) {
            float q = sigf(qv[i]);
            if (q > 0.7f) {                       // p<1 so p*q>=0.7 needs q>0.7
                float r = 0.6999f / q;            // margined prefilter threshold
                xr[i] = logf(r / (1.0f - r));
            } else {
                xr[i] = FINF;
            }
        }
        g_xmn[t] = make_float4(xr[0], xr[1], xr[2], xr[3]);
    }
}

// ---------------- kernel 2: lean scan of box_cls (R12-frozen) --------------
__global__ void __launch_bounds__(256) k_scan(const float* __restrict__ cls,
                                              const float* __restrict__ ctr) {
    int n = blockIdx.z;
    int c4 = blockIdx.x * 256 + threadIdx.x;         // chunk within image
    int c0 = blockIdx.y * CPQ;                       // first class of quarter
    float4 xm = g_xmn[n * LQ + c4];
    if (xm.x > 1.0e30f && xm.y > 1.0e30f && xm.z > 1.0e30f && xm.w > 1.0e30f)
        return;                                      // chunk fully inactive
    const float4* p = (const float4*)cls + ((size_t)n * CC + c0) * LQ + c4;
#pragma unroll 4
    for (int c = 0; c < CPQ; c++) {
        float4 xv = p[(size_t)c * LQ];
        if (xv.x > xm.x || xv.y > xm.y || xv.z > xm.z || xv.w > xm.w) {
            float xa[4] = {xv.x, xv.y, xv.z, xv.w};
            float xmn[4] = {xm.x, xm.y, xm.z, xm.w};
#pragma unroll
            for (int i = 0; i < 4; i++) {
                if (xa[i] > xmn[i]) {
                    int loc = c4 * 4 + i;
                    float q = sigf(ctr[n * LL + loc]);
                    float s = q / (1.0f + expf(-xa[i]));
                    unsigned bits = __float_as_uint(s);
                    if (bits >= BIN_BASE) {
                        unsigned seg = ((unsigned)c4) & (NSEG - 1);
                        unsigned pos = atomicAdd(&g_cnt2[n][seg], 1u);
                        if (pos < SEGCAP) {
                            unsigned idx = (unsigned)(loc * CC + (c0 + c));
                            g_cand2[n][seg][pos] = ((u64)bits << 32) | (u64)(~idx);
                        }
                        unsigned bin = ((bits - BIN_BASE) >> BIN_SHIFT) + 1u;
                        atomicAdd(&g_hist[n][bin], 1u);
                    }
                }
            }
        }
    }
}

// ---------------- kernel 3: fused threshold + gather + sort + decode -------
__global__ void k_select(const float* __restrict__ anchors,
                         const float* __restrict__ reg) {
    __shared__ u64 sh[CAP];                          // 16 KB
    __shared__ unsigned swsum[32];
    __shared__ unsigned s_thr, s_cnt;
    int n = blockIdx.x, tid = threadIdx.x;           // 1024 threads
    int warp = tid >> 5, lane = tid & 31;
    for (int t = tid; t < CAP; t += 1024) sh[t] = 0ULL;
    if (tid == 0) { s_thr = 1u; s_cnt = 0u; }
    // --- threshold bin: two-level shfl scan over 2-bin chunks (top->down) ---
    int hi = NBINS - 2 * tid;                        // top bin of this chunk
    unsigned csum = g_hist[n][hi] + g_hist[n][hi - 1];
    unsigned incl = csum;
#pragma unroll
    for (int off = 1; off < 32; off <<= 1) {
        unsigned v = __shfl_up_sync(0xffffffffu, incl, off);
        if (lane >= off) incl += v;
    }
    if (lane == 31) swsum[warp] = incl;
    __syncthreads();
    if (warp == 0) {
        unsigned w = swsum[lane];
        unsigned wi = w;
#pragma unroll
        for (int off = 1; off < 32; off <<= 1) {
            unsigned v = __shfl_up_sync(0xffffffffu, wi, off);
            if (lane >= off) wi += v;
        }
        swsum[lane] = wi - w;                        // exclusive warp base
    }
    __syncthreads();
    unsigned run = swsum[warp] + incl - csum;        // count strictly above chunk
#pragma unroll
    for (int o = 0; o < 2; o++) {
        unsigned h = g_hist[n][hi - o];
        run += h;
        if (run >= (unsigned)KTOP && run - h < (unsigned)KTOP)
            s_thr = (unsigned)(hi - o);              // unique crossing
    }
    __syncthreads();
    unsigned edge = BIN_BASE + ((s_thr - 1u) << BIN_SHIFT);
    // --- gather from segment lists (warp per segment, 2 segs per warp) ---
    for (int s = 0; s < 2; s++) {
        int seg = warp + 32 * s;
        unsigned cnt = g_cnt2[n][seg];
        if (cnt > SEGCAP) cnt = SEGCAP;
        for (unsigned j = lane; j < cnt; j += 32) {
            u64 key = g_cand2[n][seg][j];
            if ((unsigned)(key >> 32) >= edge) {
                unsigned pos = atomicAdd(&s_cnt, 1u);
                if (pos < CAP) sh[pos] = key;
            }
        }
    }
    __syncthreads();
    unsigned cnt = s_cnt;
    if (cnt > CAP) cnt = CAP;
    // --- hybrid bitonic sort desc, dynamic size 1024/2048 (cnt<=1024 common) ---
    int capx = (cnt <= 1024u) ? 1024 : 2048;         // block-uniform
    bool act = (tid < (capx >> 1));                  // warp-uniform
    u64 e0 = 0, e1 = 0;
    if (act) {
        e0 = sh[2 * tid]; e1 = sh[2 * tid + 1];
        for (int k = 2; k <= 32; k <<= 1) {          // all-register stages
            bool desc = (((2 * tid) & k) == 0);
            for (int j = k >> 1; j >= 2; j >>= 1) {
                bool keepmax = ((((2 * tid) & j) == 0) == desc);
                u64 p0 = __shfl_xor_sync(0xffffffffu, e0, j >> 1);
                u64 p1 = __shfl_xor_sync(0xffffffffu, e1, j >> 1);
                e0 = keepmax ? (e0 > p0 ? e0 : p0) : (e0 < p0 ? e0 : p0);
                e1 = keepmax ? (e1 > p1 ? e1 : p1) : (e1 < p1 ? e1 : p1);
            }
            if ((e0 < e1) == desc) { u64 tmp = e0; e0 = e1; e1 = tmp; }
        }
    }
    for (int k = 64; k <= capx; k <<= 1) {
        if (act) { sh[2 * tid] = e0; sh[2 * tid + 1] = e1; }
        __syncthreads();
        for (int j = k >> 1; j >= 32; j >>= 1) {     // smem stages
            if (act) {
                int i = ((tid & ~(j - 1)) << 1) | (tid & (j - 1));
                int p = i | j;
                u64 a = sh[i], b = sh[p];
                bool desc = ((i & k) == 0);
                if ((a < b) == desc) { sh[i] = b; sh[p] = a; }
            }
            __syncthreads();
        }
        if (act) {
            e0 = sh[2 * tid]; e1 = sh[2 * tid + 1];
            bool desc = (((2 * tid) & k) == 0);
            for (int j = 16; j >= 2; j >>= 1) {      // register tail
                bool keepmax = ((((2 * tid) & j) == 0) == desc);
                u64 p0 = __shfl_xor_sync(0xffffffffu, e0, j >> 1);
                u64 p1 = __shfl_xor_sync(0xffffffffu, e1, j >> 1);
                e0 = keepmax ? (e0 > p0 ? e0 : p0) : (e0 < p0 ? e0 : p0);
                e1 = keepmax ? (e1 > p1 ? e1 : p1) : (e1 < p1 ? e1 : p1);
            }
            if ((e0 < e1) == desc) { u64 tmp = e0; e0 = e1; e1 = tmp; }
        }
    }
    if (act) { sh[2 * tid] = e0; sh[2 * tid + 1] = e1; }
    __syncthreads();
    // --- decode top-1000 + build class->rows bitmap ---
    if (tid < KTOP) {
        if (tid < (int)cnt) {
            u64 key = sh[tid];
            unsigned bits = (unsigned)(key >> 32);
            unsigned idx = ~((unsigned)(key & 0xFFFFFFFFull));
            int loc = (int)(idx / CC);
            int c = (int)(idx % CC);
            float val = __uint_as_float(bits);
            float4 a = ((const float4*)anchors)[loc];
            float w  = a.z - a.x + 1.0f;
            float h  = a.w - a.y + 1.0f;
            float cx = a.x + 0.5f * w;
            float cy = a.y + 0.5f * h;
            float dx = reg[(size_t)(n * 4 + 0) * LL + loc] * 0.1f;
            float dy = reg[(size_t)(n * 4 + 1) * LL + loc] * 0.1f;
            float dw = fminf(reg[(size_t)(n * 4 + 2) * LL + loc] * 0.2f, XCLIP);
            float dh = fminf(reg[(size_t)(n * 4 + 3) * LL + loc] * 0.2f, XCLIP);
            float pcx = dx * w + cx;
            float pcy = dy * h + cy;
            float pw = expf(dw) * w;
            float ph = expf(dh) * h;
            float x1 = fminf(fmaxf(pcx - 0.5f * (pw - 1.0f), 0.0f), IMG_MAX);
            float y1 = fminf(fmaxf(pcy - 0.5f * (ph - 1.0f), 0.0f), IMG_MAX);
            float x2 = fminf(fmaxf(pcx + 0.5f * (pw - 1.0f), 0.0f), IMG_MAX);
            float y2 = fminf(fmaxf(pcy + 0.5f * (ph - 1.0f), 0.0f), IMG_MAX);
            g_boxes[n][tid] = make_float4(x1, y1, x2, y2);
            g_cls[n][tid] = c + 1;
            g_sc[n][tid] = sqrtf(val);
            atomicOr(&g_smatch[n][c][tid >> 5], 1u << (tid & 31));
        } else {
            g_boxes[n][tid] = make_float4(0.0f, 0.0f, 0.0f, 0.0f);
            g_cls[n][tid] = 0;
            g_sc[n][tid] = -1.0f;
        }
    }
}

// ---------------- kernel 4: suppression bitmask, stagingless (R12) ---------
__global__ void __launch_bounds__(1024) k_mask() {
    int n = blockIdx.y;
    int word = threadIdx.x & 31;
    int i = blockIdx.x * 32 + (threadIdx.x >> 5);    // row
    int ci = g_cls[n][i];
    int w0 = i >> 5;
    unsigned m = 0u;
    if (ci > 0 && word >= w0) {
        unsigned mw = g_smatch[n][ci - 1][word];
        if (word == w0) mw &= ~((2u << (i & 31)) - 1u);  // clear bits <= i
        if (mw) {
            float4 bi = g_boxes[n][i];
            float ai = fmaxf(bi.z - bi.x, 0.0f) * fmaxf(bi.w - bi.y, 0.0f);
            do {
                int b = __ffs(mw) - 1;
                mw &= mw - 1u;
                int j = word * 32 + b;
                float4 bj = g_boxes[n][j];
                float aj = fmaxf(bj.z - bj.x, 0.0f) * fmaxf(bj.w - bj.y, 0.0f);
                float lx = fmaxf(bi.x, bj.x), ly = fmaxf(bi.y, bj.y);
                float rx = fminf(bi.z, bj.z), ry = fminf(bi.w, bj.w);
                float iw = fmaxf(rx - lx, 0.0f), ih = fmaxf(ry - ly, 0.0f);
                float inter = iw * ih;
                float iou = inter / (ai + aj - inter + 1e-9f);
                if (iou > NMS_T) m |= (1u << b);
            } while (mw);
        }
    }
    g_mask[n][i][word] = m;
}

// ---------------- kernel 5: smem-staged greedy NMS + output ----------------
// 8 blocks x 512 threads, 128KB dynamic smem: stage the full mask matrix into
// smem (parallel bulk L2 reads), then warp 0 runs word-rounds on LDS (29cyc)
// instead of chained L2 round trips.
__global__ void __launch_bounds__(512) k_nms(float* __restrict__ dets,
                                             float* __restrict__ labels) {
    extern __shared__ unsigned smask[];              // [KPAD*32]
    int n = blockIdx.x, tid = threadIdx.x;
    const uint4* src = (const uint4*)&g_mask[n][0][0];
    uint4* dst = (uint4*)smask;
#pragma unroll
    for (int i = 0; i < (KPAD * 32 / 4) / 512; i++)  // 16 x uint4 per thread
        dst[tid + 512 * i] = src[tid + 512 * i];
    __syncthreads();
    if (tid >= 32) return;
    int lane = tid;
    unsigned my_valid = 0u;
#pragma unroll
    for (int b = 0; b < 32; b++)
        if (g_sc[n][lane * 32 + b] > 0.0f) my_valid |= (1u << b);
    unsigned sup = 0u;
    for (int w = 0; w < 32; w++) {
        unsigned pf[32];
#pragma unroll
        for (int b = 0; b < 32; b++) pf[b] = smask[(w * 32 + b) * 32 + lane];
        unsigned keep = 0u;
        if (lane == w) {                             // owner: serial intra-word
            unsigned s = sup;
#pragma unroll
            for (int b = 0; b < 32; b++) {
                unsigned bit = 1u << b;
                if ((my_valid & bit) && !(s & bit)) { keep |= bit; s |= pf[b]; }
            }
        }
        keep = __shfl_sync(0xffffffffu, keep, w);
#pragma unroll
        for (int b = 0; b < 32; b++)
            if (keep & (1u << b)) sup |= pf[b];
    }
    // --- lane-parallel ranked output ---
    unsigned my_keep = my_valid & ~sup;
    int pc = __popc(my_keep);
    int pref = pc;
#pragma unroll
    for (int off = 1; off < 32; off <<= 1) {
        int v = __shfl_up_sync(0xffffffffu, pref, off);
        if (lane >= off) pref += v;
    }
    pref -= pc;                                      // exclusive prefix
    unsigned rem = my_keep;
    int local = 0;
    while (rem) {
        int b = __ffs(rem) - 1;
        rem &= rem - 1u;
        int rank = pref + local;
        local++;
        if (rank < POSTN) {
            int idx = lane * 32 + b;
            float4 bx = g_boxes[n][idx];
            float* d = dets + (size_t)(n * POSTN + rank) * 5;
            d[0] = bx.x; d[1] = bx.y; d[2] = bx.z; d[3] = bx.w;
            d[4] = g_sc[n][idx];
            if (labels) labels[n * POSTN + rank] = (float)g_cls[n][idx];
        }
    }
}

// ---------------- launch -----------------------------------------------------
extern "C" void kernel_launch(void* const* d_in, const int* in_sizes, int n_in,
                              void* d_out, int out_size) {
    const float* reg  = (const float*)d_in[0];  // [8,4,160,160]
    const float* ctr  = (const float*)d_in[1];  // [8,1,160,160]
    const float* cls  = (const float*)d_in[2];  // [8,80,160,160]
    const float* anch = (const float*)d_in[3];  // [25600,4]
    float* out = (float*)d_out;
    float* dets = out;
    float* labels = (out_size >= NN * POSTN * 6) ? out + (size_t)NN * POSTN * 5 : nullptr;

    cudaFuncSetAttribute(k_nms, cudaFuncAttributeMaxDynamicSharedMemorySize,
                         NMS_SMEM);
    k_prep<<<400, 256>>>(ctr, out, out_size);
    k_scan<<<dim3(LQ / 256, NQUART, NN), 256>>>(cls, ctr);
    k_select<<<NN, 1024>>>(anch, reg);
    k_mask<<<dim3(32, NN), 1024>>>();
    k_nms<<<NN, 512, NMS_SMEM>>>(dets, labels);
}